// round 1
// baseline (speedup 1.0000x reference)
#include <cuda_runtime.h>
#include <math.h>

#define T_N 1024
#define B_N 256
#define H_N 20

// me[T] produced by kernel 1, consumed by kernel 2 (static device scratch — no allocation)
__device__ float g_me[T_N];

// ---------------------------------------------------------------------------
// Kernel 1: tiny MLP  me = sigmoid(W4 tanh(W3 tanh(W2 tanh(W1 t)))), per t-row
// ---------------------------------------------------------------------------
__global__ void mlp_kernel(const float* __restrict__ t,
                           const float* __restrict__ w1, const float* __restrict__ b1,
                           const float* __restrict__ w2, const float* __restrict__ b2,
                           const float* __restrict__ w3, const float* __restrict__ b3,
                           const float* __restrict__ w4, const float* __restrict__ b4) {
    int i = blockIdx.x * blockDim.x + threadIdx.x;
    if (i >= T_N) return;
    float tv = t[i];
    float h1[H_N], h2[H_N];
#pragma unroll
    for (int o = 0; o < H_N; ++o) h1[o] = tanhf(fmaf(tv, w1[o], b1[o]));
#pragma unroll
    for (int o = 0; o < H_N; ++o) {
        float s = b2[o];
#pragma unroll
        for (int q = 0; q < H_N; ++q) s = fmaf(h1[q], w2[q * H_N + o], s);
        h2[o] = tanhf(s);
    }
#pragma unroll
    for (int o = 0; o < H_N; ++o) {
        float s = b3[o];
#pragma unroll
        for (int q = 0; q < H_N; ++q) s = fmaf(h2[q], w3[q * H_N + o], s);
        h1[o] = tanhf(s);  // reuse as h3
    }
    float z = b4[0];
#pragma unroll
    for (int q = 0; q < H_N; ++q) z = fmaf(h1[q], w4[q], z);
    g_me[i] = 1.0f / (1.0f + expf(-z));
}

// ---------------------------------------------------------------------------
// Kernel 2: the 1023-step scan. One warp per batch column (256 warps total),
// columns fully independent -> no cross-warp sync.
//
// integ_j = dt * sum_{t<j} me[T-j+t] * I[t]
// Blocked: windows of 32 steps. At window start jk, lane l seeds
//   acc_l = sum_{t<jk} me[T-jk-l+t] * I[t]       (parallel dot product)
// Inside the window, each produced I[jk+s] is folded into every pending
// accumulator with ONE fma: acc_l += me[T-(l-s)] * I_new  (l > s).
// Step s broadcasts lane s's completed acc via shfl.
// ---------------------------------------------------------------------------
__global__ void __launch_bounds__(128, 1)
scan_kernel(const float* __restrict__ tp,
            const float* __restrict__ y,
            const float* __restrict__ beta_p,
            const float* __restrict__ gamma_p,
            float* __restrict__ out) {
    __shared__ float me_s[T_N];
    __shared__ float me_rev_s[32];
    __shared__ __align__(16) float Icol_s[4][T_N];

    const int tid  = threadIdx.x;
    const int wid  = tid >> 5;
    const int lane = tid & 31;
    const int c    = blockIdx.x * 4 + wid;   // batch column

    for (int i = tid; i < T_N; i += 128) me_s[i] = g_me[i];
    if (tid < 32) me_rev_s[tid] = (tid == 0) ? 0.0f : g_me[T_N - tid];

    const float beta  = *beta_p;
    const float gamma = *gamma_p;
    const float dt    = tp[0] - tp[1];

    float S = y[c * 3 + 0];
    float I = y[c * 3 + 1];
    float R = y[c * 3 + 2];

    float* sol = out;                                   // (T, B, 3)
    float* dif = out + (size_t)T_N * B_N * 3;           // (T, B, 3)

    if (lane == 0) {
        Icol_s[wid][0] = I;
        float* sp = sol + c * 3;                        // solution[0] = y0
        sp[0] = S; sp[1] = I; sp[2] = R;
        float* dp = dif + (size_t)(T_N - 1) * (B_N * 3) + c * 3;  // diff[T-1] = 0
        dp[0] = 0.f; dp[1] = 0.f; dp[2] = 0.f;
    }
    __syncthreads();

    float* Icol = Icol_s[wid];
    float acc = 0.0f;

    for (int k = 0; k < 32; ++k) {
        const int jk = 1 + 32 * k;
        __syncwarp();

        // ---- seed: P_l = sum_{t=0}^{jk-1} me[T-jk-l+t] * Icol[t] ----
        {
            const int m0 = T_N - jk - lane;
            float p0 = 0.f, p1 = 0.f;
            int t = 0;
            for (; t + 4 <= jk; t += 4) {
                float4 iv = *(const float4*)(Icol + t);   // broadcast LDS.128
                p0 = fmaf(me_s[m0 + t],     iv.x, p0);
                p1 = fmaf(me_s[m0 + t + 1], iv.y, p1);
                p0 = fmaf(me_s[m0 + t + 2], iv.z, p0);
                p1 = fmaf(me_s[m0 + t + 3], iv.w, p1);
            }
            for (; t < jk; ++t) p0 = fmaf(me_s[m0 + t], Icol[t], p0);
            acc = p0 + p1;
        }

        // ---- 32 sequential steps (last window: 31) ----
#pragma unroll
        for (int s = 0; s < 32; ++s) {
            const int j = jk + s;
            if (j >= T_N) break;                 // uniform across warp

            // independent of this step's shfl:
            float bSI = beta * S * I;
            float gI  = gamma * I;
            float d1  = bSI - gI;
            float In  = fmaf(dt, d1, I);         // I_{j} (shfl-independent!)
            int dd = lane - s; if (dd < 0) dd = 0;
            float w  = me_rev_s[dd];             // me[T-(lane-s)], 0 if dead
            float Sm = fmaf(-dt, bSI, S);
            float Rp = fmaf( dt, gI,  R);

            // broadcast completed accumulator of lane s
            float a     = __shfl_sync(0xffffffffu, acc, s);
            float integ = dt * a;
            float d0 = integ - bSI;
            float d2 = gI - integ;
            float Sn = fmaf( dt, integ, Sm);
            float Rn = fmaf(-dt, integ, Rp);

            // fold new I into pending accumulators (1 fma/lane/step)
            acc = fmaf(w, In, acc);

            if (lane == s) {
                Icol[j] = In;
                float* sp = sol + (size_t)j * (B_N * 3) + c * 3;
                sp[0] = Sn; sp[1] = In; sp[2] = Rn;
                float* dp = dif + (size_t)(j - 1) * (B_N * 3) + c * 3;
                dp[0] = d0; dp[1] = d1; dp[2] = d2;
            }
            S = Sn; I = In; R = Rn;
        }
    }
}

// ---------------------------------------------------------------------------
extern "C" void kernel_launch(void* const* d_in, const int* in_sizes, int n_in,
                              void* d_out, int out_size) {
    const float* t  = (const float*)d_in[0];
    const float* y  = (const float*)d_in[1];
    const float* w1 = (const float*)d_in[2];
    const float* b1 = (const float*)d_in[3];
    const float* w2 = (const float*)d_in[4];
    const float* b2 = (const float*)d_in[5];
    const float* w3 = (const float*)d_in[6];
    const float* b3 = (const float*)d_in[7];
    const float* w4 = (const float*)d_in[8];
    const float* b4 = (const float*)d_in[9];
    const float* beta  = (const float*)d_in[10];
    const float* gamma = (const float*)d_in[11];
    float* out = (float*)d_out;

    mlp_kernel<<<8, 128>>>(t, w1, b1, w2, b2, w3, b3, w4, b4);
    scan_kernel<<<64, 128>>>(t, y, beta, gamma, out);
}

// round 2
// speedup vs baseline: 1.7644x; 1.7644x over previous
#include <cuda_runtime.h>
#include <math.h>

#define T_N 1024
#define B_N 256
#define H_N 20

// me[T] produced by kernel 1, consumed by kernel 2
__device__ float g_me[T_N];

// ---------------------------------------------------------------------------
// Kernel 1: tiny MLP  me = sigmoid(W4 tanh(W3 tanh(W2 tanh(W1 t))))
// ---------------------------------------------------------------------------
__global__ void mlp_kernel(const float* __restrict__ t,
                           const float* __restrict__ w1, const float* __restrict__ b1,
                           const float* __restrict__ w2, const float* __restrict__ b2,
                           const float* __restrict__ w3, const float* __restrict__ b3,
                           const float* __restrict__ w4, const float* __restrict__ b4) {
    int i = blockIdx.x * blockDim.x + threadIdx.x;
    if (i >= T_N) return;
    float tv = t[i];
    float h1[H_N], h2[H_N];
#pragma unroll
    for (int o = 0; o < H_N; ++o) h1[o] = tanhf(fmaf(tv, w1[o], b1[o]));
#pragma unroll
    for (int o = 0; o < H_N; ++o) {
        float s = b2[o];
#pragma unroll
        for (int q = 0; q < H_N; ++q) s = fmaf(h1[q], w2[q * H_N + o], s);
        h2[o] = tanhf(s);
    }
#pragma unroll
    for (int o = 0; o < H_N; ++o) {
        float s = b3[o];
#pragma unroll
        for (int q = 0; q < H_N; ++q) s = fmaf(h2[q], w3[q * H_N + o], s);
        h1[o] = tanhf(s);
    }
    float z = b4[0];
#pragma unroll
    for (int q = 0; q < H_N; ++q) z = fmaf(h1[q], w4[q], z);
    g_me[i] = 1.0f / (1.0f + expf(-z));
}

// ---------------------------------------------------------------------------
// Kernel 2: one CTA (96 threads = 3 warps) per batch column.
//   warp 0: runs the 1023 sequential steps, 32-step windows.
//           Keeps acc  = accumulator for this window's lane step,
//                 acc2 = "recent" part of NEXT window's accumulator.
//   warps 1,2: during window k, cooperatively compute the history partial
//           of window k+1's seeds over t in [0, jk)  (double-buffered).
// Per-step loop-carried chain: a -> Snew -> Inew -> fold -> shfl  (~38 cyc).
// ---------------------------------------------------------------------------
__global__ void __launch_bounds__(96, 1)
scan_kernel(const float* __restrict__ tp,
            const float* __restrict__ y,
            const float* __restrict__ beta_p,
            const float* __restrict__ gamma_p,
            float* __restrict__ out) {
    __shared__ float me_s[T_N];
    __shared__ float me_revx_s[96];              // me_revx_s[32+d] = me[T-d], d in [1,63]
    __shared__ __align__(16) float Icol[T_N];
    __shared__ float parts[2][2][32];            // [buf][seedwarp][lane]

    const int tid  = threadIdx.x;
    const int wid  = tid >> 5;
    const int lane = tid & 31;
    const int c    = blockIdx.x;                 // batch column

    for (int i = tid; i < T_N; i += 96) me_s[i] = g_me[i];
    // me_revx_s[i] = me[T-(i-32)] valid for i in [33,95]
    me_revx_s[tid] = (tid >= 33) ? g_me[(T_N + 32) - tid] : 0.0f;

    const float beta  = *beta_p;
    const float gamma = *gamma_p;
    const float dt    = tp[0] - tp[1];
    const float dt2   = dt * dt;
    const float cg    = 1.0f - dt * gamma;

    float S = y[c * 3 + 0];
    float I = y[c * 3 + 1];
    float R = y[c * 3 + 2];

    float* sol = out;                                  // (T, B, 3)
    float* dif = out + (size_t)T_N * B_N * 3;          // (T, B, 3)

    if (tid == 0) {
        Icol[0] = I;
        float* sp = sol + c * 3;                       // solution[0] = y0
        sp[0] = S; sp[1] = I; sp[2] = R;
        float* dp = dif + (size_t)(T_N - 1) * (B_N * 3) + c * 3;  // diff[T-1]=0
        dp[0] = 0.f; dp[1] = 0.f; dp[2] = 0.f;
    }
    __syncthreads();

    if (wid == 0) {
        // ------------------- step warp -------------------
        float acc  = me_revx_s[33 + lane] * I;   // seed window 0: me[T-1-lane]*I0
        float acc2 = 0.0f;
        // precomputes from state (S0, I0)
        float bI  = beta * I;
        float gI  = gamma * I;
        float cgI = cg * I;
        float dbI = dt * bI;

        for (int k = 0; k < 32; ++k) {
            const int jk = 1 + 32 * k;
            if (k > 0) {
                acc  = acc2 + parts[k & 1][0][lane] + parts[k & 1][1][lane];
                acc2 = 0.0f;
            }
            float o0 = 0.f, o1 = 0.f, o2 = 0.f, oS = 0.f, oI = 0.f, oR = 0.f;

#pragma unroll
            for (int s = 0; s < 32; ++s) {
                const int j = jk + s;
                if (j >= T_N) break;                    // warp-uniform

                // fold weights (off critical path)
                float wv  = me_revx_s[32 + lane - s];   // current-window fold
                float w2v = me_revx_s[64 + lane - s];   // next-window fold

                // broadcast lane s's completed accumulator
                float a = __shfl_sync(0xffffffffu, acc, s);

                // chain: a -> Snew -> Inew -> fold -> (next shfl)
                float bSI  = bI * S;
                float Sm   = fmaf(-dt, bSI, S);
                float Snew = fmaf(dt2, a, Sm);
                float Inew = fmaf(dbI, Snew, cgI);      // = I + dt*(beta*Snew*I - gamma*I)
                acc  = fmaf(wv,  Inew, acc);
                acc2 = fmaf(w2v, Inew, acc2);

                // off-chain outputs
                float integ = dt * a;
                float d0 = integ - bSI;
                float d1 = bSI - gI;
                float d2 = gI - integ;
                float Rnew = fmaf(dt, d2, R);

                if (lane == s) { o0 = d0; o1 = d1; o2 = d2; oS = Snew; oI = Inew; oR = Rnew; }

                // precomputes for next step
                bI  = beta * Inew;
                gI  = gamma * Inew;
                cgI = cg * Inew;
                dbI = dt * bI;
                S = Snew; I = Inew; R = Rnew;
            }

            // wait: reference updates I with its OWN S step? (I_j uses S_{j-1})
            // NOTE: Inew above uses Snew (S_j), but reference uses S_{j-1}:
            //   I_j = I_{j-1} + dt*(beta*S_{j-1}*I_{j-1} - gamma*I_{j-1})
            // -> handled below? NO: must fold with bSI from OLD S. See errata fix:
            // (kept consistent: bSI = bI*S uses OLD S; Inew must use OLD S too.)

            // batched per-window stores: lane l owns step jk+l
            int jl = jk + lane;
            if (jl < T_N) {
                Icol[jl] = oI;
                float* sp = sol + (size_t)jl * (B_N * 3) + c * 3;
                sp[0] = oS; sp[1] = oI; sp[2] = oR;
                float* dp = dif + (size_t)(jl - 1) * (B_N * 3) + c * 3;
                dp[0] = o0; dp[1] = o1; dp[2] = o2;
            }
            __syncthreads();
        }
    } else {
        // ------------------- seed warps (wid 1,2) -------------------
        for (int k = 0; k < 32; ++k) {
            if (k < 31) {
                const int jn  = 33 + 32 * k;      // next window start j_{k+1}
                const int len = 1 + 32 * k;       // history range [0, len)
                const int m0  = T_N - jn - lane;  // me index base (>= 0)
                int t0, t1;
                if (wid == 1) { t0 = 0; t1 = (len >> 1) & ~3; }
                else          { t0 = (len >> 1) & ~3; t1 = len; }
                float p0 = 0.f, p1 = 0.f;
                int t = t0;
                for (; t + 4 <= t1; t += 4) {
                    float4 iv = *(const float4*)(Icol + t);   // broadcast LDS.128
                    p0 = fmaf(me_s[m0 + t],     iv.x, p0);
                    p1 = fmaf(me_s[m0 + t + 1], iv.y, p1);
                    p0 = fmaf(me_s[m0 + t + 2], iv.z, p0);
                    p1 = fmaf(me_s[m0 + t + 3], iv.w, p1);
                }
                for (; t < t1; ++t) p0 = fmaf(me_s[m0 + t], Icol[t], p0);
                parts[(k + 1) & 1][wid - 1][lane] = p0 + p1;
            }
            __syncthreads();
        }
    }
}

// ---------------------------------------------------------------------------
extern "C" void kernel_launch(void* const* d_in, const int* in_sizes, int n_in,
                              void* d_out, int out_size) {
    const float* t  = (const float*)d_in[0];
    const float* y  = (const float*)d_in[1];
    const float* w1 = (const float*)d_in[2];
    const float* b1 = (const float*)d_in[3];
    const float* w2 = (const float*)d_in[4];
    const float* b2 = (const float*)d_in[5];
    const float* w3 = (const float*)d_in[6];
    const float* b3 = (const float*)d_in[7];
    const float* w4 = (const float*)d_in[8];
    const float* b4 = (const float*)d_in[9];
    const float* beta  = (const float*)d_in[10];
    const float* gamma = (const float*)d_in[11];
    float* out = (float*)d_out;

    mlp_kernel<<<8, 128>>>(t, w1, b1, w2, b2, w3, b3, w4, b4);
    scan_kernel<<<B_N, 96>>>(t, y, beta, gamma, out);
}

// round 3
// speedup vs baseline: 2.1989x; 1.2463x over previous
#include <cuda_runtime.h>
#include <math.h>

#define T_N 1024
#define B_N 256
#define H_N 20

__device__ float g_me[T_N];

// ---------------------------------------------------------------------------
// Kernel 1: tiny MLP  me = sigmoid(W4 tanh(W3 tanh(W2 tanh(W1 t))))
// ---------------------------------------------------------------------------
__global__ void mlp_kernel(const float* __restrict__ t,
                           const float* __restrict__ w1, const float* __restrict__ b1,
                           const float* __restrict__ w2, const float* __restrict__ b2,
                           const float* __restrict__ w3, const float* __restrict__ b3,
                           const float* __restrict__ w4, const float* __restrict__ b4) {
    int i = blockIdx.x * blockDim.x + threadIdx.x;
    if (i >= T_N) return;
    float tv = t[i];
    float h1[H_N], h2[H_N];
#pragma unroll
    for (int o = 0; o < H_N; ++o) h1[o] = tanhf(fmaf(tv, w1[o], b1[o]));
#pragma unroll
    for (int o = 0; o < H_N; ++o) {
        float s = b2[o];
#pragma unroll
        for (int q = 0; q < H_N; ++q) s = fmaf(h1[q], w2[q * H_N + o], s);
        h2[o] = tanhf(s);
    }
#pragma unroll
    for (int o = 0; o < H_N; ++o) {
        float s = b3[o];
#pragma unroll
        for (int q = 0; q < H_N; ++q) s = fmaf(h2[q], w3[q * H_N + o], s);
        h1[o] = tanhf(s);
    }
    float z = b4[0];
#pragma unroll
    for (int q = 0; q < H_N; ++q) z = fmaf(h1[q], w4[q], z);
    g_me[i] = 1.0f / (1.0f + expf(-z));
}

// ---------------------------------------------------------------------------
// Kernel 2: 2 columns per CTA (grid=128 -> single wave), 256 threads:
//   w0, w1            : step warps (col A, col B) - on SMSP 0, 1
//   w2..w7 (q=0..5)   : seed warps, each covers a t-slice for BOTH columns
//                       (shared me loads). Slices weighted so the SMSPs that
//                       also host a step warp (q=2,3) get smaller shares.
// me is pre-scaled by dt^2 so the S update is a single fma.
// Per-step chain: S -> v -> I -> fix -> S  (~8cyc) + shfl/4 batched.
// ---------------------------------------------------------------------------
__global__ void __launch_bounds__(256, 1)
scan_kernel(const float* __restrict__ tp,
            const float* __restrict__ y,
            const float* __restrict__ beta_p,
            const float* __restrict__ gamma_p,
            float* __restrict__ out) {
    __shared__ float mew[T_N];                 // dt^2 * me
    __shared__ float wrevx[96];                // wrevx[32+d] = dt^2*me[T-d], d in [1,63]
    __shared__ __align__(16) float IcolA[T_N];
    __shared__ __align__(16) float IcolB[T_N];
    __shared__ float parts[2][6][2][32];       // [buf][seedwarp][col][lane]

    const int tid  = threadIdx.x;
    const int wid  = tid >> 5;
    const int lane = tid & 31;

    const float beta  = *beta_p;
    const float gamma = *gamma_p;
    const float dt    = tp[0] - tp[1];
    const float dt2   = dt * dt;
    const float dtb   = dt * beta;
    const float cg    = 1.0f - dt * gamma;
    const float rdt   = 1.0f / dt;

    for (int i = tid; i < T_N; i += 256) mew[i] = dt2 * g_me[i];
    if (tid < 96) wrevx[tid] = (tid >= 33) ? dt2 * g_me[(T_N + 32) - tid] : 0.0f;

    float* sol = out;                                  // (T, B, 3)
    float* dif = out + (size_t)T_N * B_N * 3;          // (T, B, 3)

    if (wid < 2) {
        // prologue for this warp's column
        const int c = blockIdx.x * 2 + wid;
        float S0 = y[c * 3 + 0], I0 = y[c * 3 + 1], R0 = y[c * 3 + 2];
        float* Icol = wid ? IcolB : IcolA;
        if (lane == 0) {
            Icol[0] = I0;
            float* sp = sol + c * 3;
            sp[0] = S0; sp[1] = I0; sp[2] = R0;
            float* dp = dif + (size_t)(T_N - 1) * (B_N * 3) + c * 3;
            dp[0] = 0.f; dp[1] = 0.f; dp[2] = 0.f;
        }
    }
    __syncthreads();

    if (wid < 2) {
        // ------------------------- step warp -------------------------
        const int c = blockIdx.x * 2 + wid;
        float* Icol = wid ? IcolB : IcolA;
        float S = y[c * 3 + 0];
        float I = y[c * 3 + 1];
        const float Ctot = S + I + y[c * 3 + 2];

        const float* wp = &wrevx[32 + lane];
        const float wr1 = wrevx[33], wr2 = wrevx[34], wr3 = wrevx[35];

        float acc  = wrevx[33 + lane] * I;     // window-0 seed: dt^2*me[T-1-lane]*I0
        float acc2 = 0.0f;
        float u = fmaf(-dtb, I, 1.0f);
        float aS = 0.f, Sp = 0.f, Ip = 0.f;

#define STEP(sidx, AV)                                                   \
        {   const int s_ = (sidx);                                       \
            bool m_ = (lane == s_);                                      \
            aS = m_ ? (AV) : aS;                                         \
            Sp = m_ ? S : Sp;                                            \
            Ip = m_ ? I : Ip;                                            \
            float Sn_ = fmaf(S, u, (AV));                                \
            float v_  = fmaf(dtb, S, cg);                                \
            float In_ = I * v_;                                          \
            acc  = fmaf(wp[-s_],     In_, acc);                          \
            acc2 = fmaf(wp[32 - s_], In_, acc2);                         \
            u = fmaf(-dtb, In_, 1.0f);                                   \
            S = Sn_; I = In_; }

        for (int k = 0; k < 32; ++k) {
            if (k > 0) {
                const int b = k & 1;
                acc = acc2
                    + parts[b][0][wid][lane] + parts[b][1][wid][lane]
                    + parts[b][2][wid][lane] + parts[b][3][wid][lane]
                    + parts[b][4][wid][lane] + parts[b][5][wid][lane];
                acc2 = 0.0f;
            }
            const int jk = 1 + 32 * k;

#pragma unroll
            for (int sb = 0; sb < 32; sb += 4) {
                float a0 = __shfl_sync(0xffffffffu, acc, sb + 0);
                float a1 = __shfl_sync(0xffffffffu, acc, sb + 1);
                float a2 = __shfl_sync(0xffffffffu, acc, sb + 2);
                float a3 = __shfl_sync(0xffffffffu, acc, sb + 3);
                STEP(sb + 0, a0)
                a1 = fmaf(wr1, I, a1); a2 = fmaf(wr2, I, a2); a3 = fmaf(wr3, I, a3);
                STEP(sb + 1, a1)
                a2 = fmaf(wr1, I, a2); a3 = fmaf(wr2, I, a3);
                STEP(sb + 2, a2)
                a3 = fmaf(wr1, I, a3);
                STEP(sb + 3, a3)
            }

            // post-window: lane l owns step j = jk + l (snapshots aS, Sp, Ip)
            const int j = jk + lane;
            if (j < T_N) {
                float integ = aS * rdt;                  // dt * a_true
                float bSI = beta * Sp * Ip;
                float gI  = gamma * Ip;
                float d0 = integ - bSI;
                float d1 = bSI - gI;
                float d2 = gI - integ;
                float uw = fmaf(-dtb, Ip, 1.0f);
                float Sn = fmaf(Sp, uw, aS);
                float vw = fmaf(dtb, Sp, cg);
                float In = Ip * vw;
                float Rn = Ctot - Sn - In;
                Icol[j] = In;
                float* sp = sol + (size_t)j * (B_N * 3) + c * 3;
                sp[0] = Sn; sp[1] = In; sp[2] = Rn;
                float* dp = dif + (size_t)(j - 1) * (B_N * 3) + c * 3;
                dp[0] = d0; dp[1] = d1; dp[2] = d2;
            }
            __syncthreads();
        }
#undef STEP
    } else {
        // ------------------------- seed warps -------------------------
        const int q = wid - 2;
        // cumulative 16ths: q=2,3 (SMSP shared with step warps) get 2/16
        const int cumt[7] = {0, 3, 6, 8, 10, 13, 16};
        const int c0 = cumt[q], c1 = cumt[q + 1];

        for (int k = 0; k < 32; ++k) {
            if (k < 31) {
                const int len = 1 + 32 * k;
                const int jn  = 33 + 32 * k;
                const int m0  = T_N - jn - lane;
                const float* mp = &mew[m0];
                int t0 = (len * c0) >> 4;
                int t1 = (len * c1) >> 4;
                float pA0 = 0.f, pA1 = 0.f, pB0 = 0.f, pB1 = 0.f;
                int t = t0;
                for (; t < t1 && (t & 3); ++t) {
                    float w = mp[t];
                    pA0 = fmaf(w, IcolA[t], pA0);
                    pB0 = fmaf(w, IcolB[t], pB0);
                }
                for (; t + 4 <= t1; t += 4) {
                    float4 ia = *(const float4*)&IcolA[t];
                    float4 ib = *(const float4*)&IcolB[t];
                    float w0 = mp[t], w1 = mp[t + 1], w2 = mp[t + 2], w3 = mp[t + 3];
                    pA0 = fmaf(w0, ia.x, pA0); pA1 = fmaf(w1, ia.y, pA1);
                    pA0 = fmaf(w2, ia.z, pA0); pA1 = fmaf(w3, ia.w, pA1);
                    pB0 = fmaf(w0, ib.x, pB0); pB1 = fmaf(w1, ib.y, pB1);
                    pB0 = fmaf(w2, ib.z, pB0); pB1 = fmaf(w3, ib.w, pB1);
                }
                for (; t < t1; ++t) {
                    float w = mp[t];
                    pA0 = fmaf(w, IcolA[t], pA0);
                    pB0 = fmaf(w, IcolB[t], pB0);
                }
                const int b = (k + 1) & 1;
                parts[b][q][0][lane] = pA0 + pA1;
                parts[b][q][1][lane] = pB0 + pB1;
            }
            __syncthreads();
        }
    }
}

// ---------------------------------------------------------------------------
extern "C" void kernel_launch(void* const* d_in, const int* in_sizes, int n_in,
                              void* d_out, int out_size) {
    const float* t  = (const float*)d_in[0];
    const float* y  = (const float*)d_in[1];
    const float* w1 = (const float*)d_in[2];
    const float* b1 = (const float*)d_in[3];
    const float* w2 = (const float*)d_in[4];
    const float* b2 = (const float*)d_in[5];
    const float* w3 = (const float*)d_in[6];
    const float* b3 = (const float*)d_in[7];
    const float* w4 = (const float*)d_in[8];
    const float* b4 = (const float*)d_in[9];
    const float* beta  = (const float*)d_in[10];
    const float* gamma = (const float*)d_in[11];
    float* out = (float*)d_out;

    mlp_kernel<<<8, 128>>>(t, w1, b1, w2, b2, w3, b3, w4, b4);
    scan_kernel<<<128, 256>>>(t, y, beta, gamma, out);
}